// round 1
// baseline (speedup 1.0000x reference)
#include <cuda_runtime.h>

// Problem: out[b] = softmax_rows(X_b X_b^T), X: [4, 4096, 64] fp32.
// Strategy R0:
//   Kernel 1: symmetric tiled fp32 GEMM -> 256MB __device__ scratch (only ti<=tj
//             tiles computed; mirror tile written for ti<tj).
//   Kernel 2: one block per row: load row (16 floats/thread), block-reduce max,
//             exp, block-reduce sum, normalized write.

#define NTOK 4096
#define DDIM 64
#define BT   128   // output tile (BT x BT)
#define KC   32    // k-chunk (two chunks cover D=64), keeps smem < 48KB

__device__ float g_S[(size_t)4 * NTOK * NTOK];  // 256 MB scratch

__global__ __launch_bounds__(256) void gemm_sym(const float* __restrict__ X) {
    const int tj = blockIdx.x;
    const int ti = blockIdx.y;
    const int b  = blockIdx.z;
    if (ti > tj) return;  // symmetric: compute upper-triangular tiles only

    __shared__ __align__(16) float As[KC][BT + 4];
    __shared__ __align__(16) float Bs[KC][BT + 4];

    const int tid = threadIdx.x;
    const int tx  = tid & 15;   // 16 col-groups of 8
    const int ty  = tid >> 4;   // 16 row-groups of 8

    float acc[8][8];
#pragma unroll
    for (int i = 0; i < 8; i++)
#pragma unroll
        for (int j = 0; j < 8; j++) acc[i][j] = 0.0f;

    const float* Xb = X + (size_t)b * NTOK * DDIM;
    const int r0 = ti * BT;
    const int c0 = tj * BT;

    for (int kk = 0; kk < DDIM; kk += KC) {
        // Load A tile (BT x KC) transposed into As[k][i]; 1024 float4s, 256 thr.
#pragma unroll
        for (int it = 0; it < 4; it++) {
            int idx = tid + it * 256;
            int i  = idx & (BT - 1);
            int c4 = idx >> 7;  // 0..7 (float4 column index within chunk)
            float4 v = *reinterpret_cast<const float4*>(
                Xb + (size_t)(r0 + i) * DDIM + kk + c4 * 4);
            As[c4 * 4 + 0][i] = v.x;
            As[c4 * 4 + 1][i] = v.y;
            As[c4 * 4 + 2][i] = v.z;
            As[c4 * 4 + 3][i] = v.w;
        }
#pragma unroll
        for (int it = 0; it < 4; it++) {
            int idx = tid + it * 256;
            int i  = idx & (BT - 1);
            int c4 = idx >> 7;
            float4 v = *reinterpret_cast<const float4*>(
                Xb + (size_t)(c0 + i) * DDIM + kk + c4 * 4);
            Bs[c4 * 4 + 0][i] = v.x;
            Bs[c4 * 4 + 1][i] = v.y;
            Bs[c4 * 4 + 2][i] = v.z;
            Bs[c4 * 4 + 3][i] = v.w;
        }
        __syncthreads();

#pragma unroll 8
        for (int k = 0; k < KC; k++) {
            float a[8], bb[8];
            *(float4*)&a[0]  = *(const float4*)&As[k][ty * 8];
            *(float4*)&a[4]  = *(const float4*)&As[k][ty * 8 + 4];
            *(float4*)&bb[0] = *(const float4*)&Bs[k][tx * 8];
            *(float4*)&bb[4] = *(const float4*)&Bs[k][tx * 8 + 4];
#pragma unroll
            for (int i = 0; i < 8; i++)
#pragma unroll
                for (int j = 0; j < 8; j++)
                    acc[i][j] = fmaf(a[i], bb[j], acc[i][j]);
        }
        __syncthreads();
    }

    // Epilogue: write tile (and mirror if off-diagonal).
    float* Sb = g_S + (size_t)b * NTOK * NTOK;
    const int r = r0 + ty * 8;
    const int c = c0 + tx * 8;

#pragma unroll
    for (int i = 0; i < 8; i++) {
        float4 v0 = make_float4(acc[i][0], acc[i][1], acc[i][2], acc[i][3]);
        float4 v1 = make_float4(acc[i][4], acc[i][5], acc[i][6], acc[i][7]);
        float* p = Sb + (size_t)(r + i) * NTOK + c;
        *reinterpret_cast<float4*>(p)     = v0;
        *reinterpret_cast<float4*>(p + 4) = v1;
    }
    if (ti != tj) {
#pragma unroll
        for (int j = 0; j < 8; j++) {
            float4 u0 = make_float4(acc[0][j], acc[1][j], acc[2][j], acc[3][j]);
            float4 u1 = make_float4(acc[4][j], acc[5][j], acc[6][j], acc[7][j]);
            float* p = Sb + (size_t)(c + j) * NTOK + r;
            *reinterpret_cast<float4*>(p)     = u0;
            *reinterpret_cast<float4*>(p + 4) = u1;
        }
    }
}

__global__ __launch_bounds__(256) void softmax_rows(float* __restrict__ out) {
    const size_t row = blockIdx.x;  // 0 .. 4*4096-1
    const float* src = g_S + row * NTOK;
    float* dst       = out + row * NTOK;
    const int t = threadIdx.x;

    float v[16];
#pragma unroll
    for (int p = 0; p < 4; p++)
        *(float4*)&v[p * 4] =
            *(const float4*)&src[(size_t)p * 1024 + t * 4];

    // --- row max ---
    float m = v[0];
#pragma unroll
    for (int i = 1; i < 16; i++) m = fmaxf(m, v[i]);
#pragma unroll
    for (int o = 16; o > 0; o >>= 1)
        m = fmaxf(m, __shfl_xor_sync(0xffffffffu, m, o));

    __shared__ float red[8];
    if ((t & 31) == 0) red[t >> 5] = m;
    __syncthreads();
    float mm = red[0];
#pragma unroll
    for (int w = 1; w < 8; w++) mm = fmaxf(mm, red[w]);
    __syncthreads();  // red reused below

    // --- exp + row sum ---
    float s = 0.0f;
#pragma unroll
    for (int i = 0; i < 16; i++) {
        v[i] = __expf(v[i] - mm);
        s += v[i];
    }
#pragma unroll
    for (int o = 16; o > 0; o >>= 1)
        s += __shfl_xor_sync(0xffffffffu, s, o);
    if ((t & 31) == 0) red[t >> 5] = s;
    __syncthreads();
    float ss = 0.0f;
#pragma unroll
    for (int w = 0; w < 8; w++) ss += red[w];

    const float inv = 1.0f / ss;
#pragma unroll
    for (int i = 0; i < 16; i++) v[i] *= inv;

#pragma unroll
    for (int p = 0; p < 4; p++)
        *(float4*)&dst[(size_t)p * 1024 + t * 4] = *(float4*)&v[p * 4];
}

extern "C" void kernel_launch(void* const* d_in, const int* in_sizes, int n_in,
                              void* d_out, int out_size) {
    const float* X = (const float*)d_in[0];
    float* out     = (float*)d_out;
    (void)in_sizes; (void)n_in; (void)out_size;

    gemm_sym<<<dim3(NTOK / BT, NTOK / BT, 4), 256>>>(X);
    softmax_rows<<<4 * NTOK, 256>>>(out);
}

// round 3
// speedup vs baseline: 1.3835x; 1.3835x over previous
#include <cuda_runtime.h>
#include <cuda_bf16.h>

// out[b] = softmax_rows(X_b X_b^T), X: [4, 4096, 64] fp32.
// R3: k0 split X -> bf16 hi/lo; k1 mma.sync bf16 GEMM (hi*hi + hi*lo + lo*hi),
//     symmetric tiles only (mirror written transposed) -> 256MB scratch;
//     k2 row softmax (DRAM-bound, unchanged).
// NOTE: harness ptxas target is sm_103 (no 'a') -> no tcgen05/TMEM. Use
//       portable ldmatrix + mma.sync (HMMA path).

#define NTOK 4096
#define DDIM 64
#define BT   128
#define NB   4

__device__ float         g_S [(size_t)NB * NTOK * NTOK];   // 256 MB scratch
__device__ __nv_bfloat16 g_hi[(size_t)NB * NTOK * DDIM];   // 4 MB
__device__ __nv_bfloat16 g_lo[(size_t)NB * NTOK * DDIM];   // 4 MB

#define SW128(off) ((off) ^ (((off) >> 3) & 0x70))

__device__ __forceinline__ unsigned smem_u32(const void* p) {
    unsigned a;
    asm("{ .reg .u64 t; cvta.to.shared.u64 t, %1; cvt.u32.u64 %0, t; }"
        : "=r"(a) : "l"(p));
    return a;
}
__device__ __forceinline__ void ldsm4(unsigned* r, unsigned addr) {
    asm volatile("ldmatrix.sync.aligned.m8n8.x4.shared.b16 {%0,%1,%2,%3}, [%4];"
                 : "=r"(r[0]), "=r"(r[1]), "=r"(r[2]), "=r"(r[3]) : "r"(addr));
}
__device__ __forceinline__ void mma16816(float* d, const unsigned* a,
                                         unsigned b0, unsigned b1) {
    asm volatile(
        "mma.sync.aligned.m16n8k16.row.col.f32.bf16.bf16.f32 "
        "{%0,%1,%2,%3}, {%4,%5,%6,%7}, {%8,%9}, {%0,%1,%2,%3};"
        : "+f"(d[0]), "+f"(d[1]), "+f"(d[2]), "+f"(d[3])
        : "r"(a[0]), "r"(a[1]), "r"(a[2]), "r"(a[3]), "r"(b0), "r"(b1));
}

// ---------------- k0: split fp32 -> bf16 hi + lo ----------------
__global__ __launch_bounds__(256) void split_bf16(const float* __restrict__ X) {
    size_t i = ((size_t)blockIdx.x * blockDim.x + threadIdx.x) * 4;
    float4 v = *reinterpret_cast<const float4*>(X + i);
    __nv_bfloat162 h01 = __floats2bfloat162_rn(v.x, v.y);
    __nv_bfloat162 h23 = __floats2bfloat162_rn(v.z, v.w);
    __nv_bfloat162 l01 = __floats2bfloat162_rn(v.x - __low2float(h01),
                                               v.y - __high2float(h01));
    __nv_bfloat162 l23 = __floats2bfloat162_rn(v.z - __low2float(h23),
                                               v.w - __high2float(h23));
    *reinterpret_cast<__nv_bfloat162*>(g_hi + i)     = h01;
    *reinterpret_cast<__nv_bfloat162*>(g_hi + i + 2) = h23;
    *reinterpret_cast<__nv_bfloat162*>(g_lo + i)     = l01;
    *reinterpret_cast<__nv_bfloat162*>(g_lo + i + 2) = l23;
}

// ---------------- k1: mma.sync GEMM, 128x128 tile per CTA ----------------
// dyn smem union:
//   operands: Ah @0, Al @16K, Bh @32K, Bl @48K (each 128 rows x 128 B, SW128)
//   stage:    float[128][132]  (67584 B)
#define STG_LD     132
#define SMEM_BYTES 67584

__device__ __forceinline__ void load_tile(char* dst, const __nv_bfloat16* src,
                                          int tid) {
    const uint4* s = reinterpret_cast<const uint4*>(src);
#pragma unroll
    for (int it = 0; it < 4; it++) {
        int i = it * 256 + tid;                 // 0..1023 16B chunks
        unsigned off = (unsigned)i * 16u;
        *reinterpret_cast<uint4*>(dst + SW128(off)) = s[i];
    }
}

__global__ __launch_bounds__(256) void gemm_mma() {
    const int tj = blockIdx.x, ti = blockIdx.y, b = blockIdx.z;
    if (ti > tj) return;  // symmetric

    extern __shared__ __align__(1024) char smem[];
    float* stage = reinterpret_cast<float*>(smem);
    const unsigned sm = smem_u32(smem);

    const int tid  = threadIdx.x;
    const int wid  = tid >> 5;
    const int lane = tid & 31;
    const int mrow0 = (wid >> 1) * 32;   // 4 warp-rows of 32
    const int ncol0 = (wid & 1) * 64;    // 2 warp-cols of 64

    const size_t aoff = ((size_t)b * NTOK + (size_t)ti * BT) * DDIM;
    const size_t boff = ((size_t)b * NTOK + (size_t)tj * BT) * DDIM;
    load_tile(smem,         g_hi + aoff, tid);
    load_tile(smem + 16384, g_lo + aoff, tid);
    load_tile(smem + 32768, g_hi + boff, tid);
    load_tile(smem + 49152, g_lo + boff, tid);
    __syncthreads();

    float acc[2][8][4];
#pragma unroll
    for (int mf = 0; mf < 2; mf++)
#pragma unroll
        for (int nf = 0; nf < 8; nf++)
#pragma unroll
            for (int e = 0; e < 4; e++) acc[mf][nf][e] = 0.0f;

    // lane-invariant parts of ldmatrix addressing
    const int lrow  = lane & 15;          // row/n within 16-block
    const int lkoff = (lane >> 4) * 8;    // k half select (x4 tiles 2..3)

    const unsigned aBase[3] = { sm, sm, sm + 16384 };          // Ah, Ah, Al
    const unsigned bBase[3] = { sm + 32768, sm + 49152, sm + 32768 };  // Bh, Bl, Bh

#pragma unroll
    for (int p = 0; p < 3; p++) {
        const unsigned ab = aBase[p], bb = bBase[p];
#pragma unroll
        for (int ks = 0; ks < 4; ks++) {
            const int kk = ks * 16;
            unsigned a[2][4];
#pragma unroll
            for (int mf = 0; mf < 2; mf++) {
                unsigned byte = (unsigned)(mrow0 + mf * 16 + lrow) * 128u
                              + (unsigned)(kk + lkoff) * 2u;
                ldsm4(a[mf], ab + SW128(byte));
            }
#pragma unroll
            for (int nq = 0; nq < 4; nq++) {
                unsigned r[4];
                unsigned byte = (unsigned)(ncol0 + nq * 16 + lrow) * 128u
                              + (unsigned)(kk + lkoff) * 2u;
                ldsm4(r, bb + SW128(byte));
                // r0:(n0-7,k0-7) r1:(n8-15,k0-7) r2:(n0-7,k8-15) r3:(n8-15,k8-15)
#pragma unroll
                for (int mf = 0; mf < 2; mf++) {
                    mma16816(acc[mf][nq * 2 + 0], a[mf], r[0], r[2]);
                    mma16816(acc[mf][nq * 2 + 1], a[mf], r[1], r[3]);
                }
            }
        }
    }
    __syncthreads();  // operands dead; smem becomes stage

    // ---- stage normal tile, coalesced write ----
    const int fr = lane >> 2;          // 0..7
    const int fc = (lane & 3) * 2;     // 0,2,4,6
#pragma unroll
    for (int mf = 0; mf < 2; mf++)
#pragma unroll
        for (int nf = 0; nf < 8; nf++) {
            int r = mrow0 + mf * 16 + fr;
            int c = ncol0 + nf * 8 + fc;
            float* s0 = stage + (size_t)r * STG_LD + c;
            s0[0] = acc[mf][nf][0];
            s0[1] = acc[mf][nf][1];
            s0[8 * STG_LD]     = acc[mf][nf][2];
            s0[8 * STG_LD + 1] = acc[mf][nf][3];
        }
    __syncthreads();

    float* Sb = g_S + (size_t)b * NTOK * NTOK;
    {
        float* dst = Sb + (size_t)ti * BT * NTOK + (size_t)tj * BT;
        const int c4 = (tid & 31) * 4, rq = tid >> 5;
#pragma unroll
        for (int it = 0; it < 16; it++) {
            int r = rq + it * 8;
            *reinterpret_cast<float4*>(dst + (size_t)r * NTOK + c4) =
                *reinterpret_cast<const float4*>(stage + (size_t)r * STG_LD + c4);
        }
    }

    if (ti == tj) return;

    // ---- stage transposed tile, coalesced mirror write ----
    __syncthreads();
#pragma unroll
    for (int mf = 0; mf < 2; mf++)
#pragma unroll
        for (int nf = 0; nf < 8; nf++) {
            int r = mrow0 + mf * 16 + fr;
            int c = ncol0 + nf * 8 + fc;
            float* s0 = stage + (size_t)c * STG_LD + r;     // [c][r]
            s0[0]           = acc[mf][nf][0];
            s0[STG_LD]      = acc[mf][nf][1];               // [c+1][r]
            s0[8]           = acc[mf][nf][2];               // [c][r+8]
            s0[STG_LD + 8]  = acc[mf][nf][3];               // [c+1][r+8]
        }
    __syncthreads();
    {
        float* dst = Sb + (size_t)tj * BT * NTOK + (size_t)ti * BT;
        const int c4 = (tid & 31) * 4, rq = tid >> 5;
#pragma unroll
        for (int it = 0; it < 16; it++) {
            int r = rq + it * 8;
            *reinterpret_cast<float4*>(dst + (size_t)r * NTOK + c4) =
                *reinterpret_cast<const float4*>(stage + (size_t)r * STG_LD + c4);
        }
    }
}

// ---------------- k2: row softmax (DRAM-bound) ----------------
__global__ __launch_bounds__(256) void softmax_rows(float* __restrict__ out) {
    const size_t row = blockIdx.x;
    const float* src = g_S + row * NTOK;
    float* dst       = out + row * NTOK;
    const int t = threadIdx.x;

    float v[16];
#pragma unroll
    for (int p = 0; p < 4; p++)
        *(float4*)&v[p * 4] = *(const float4*)&src[(size_t)p * 1024 + t * 4];

    float m = v[0];
#pragma unroll
    for (int i = 1; i < 16; i++) m = fmaxf(m, v[i]);
#pragma unroll
    for (int o = 16; o > 0; o >>= 1) m = fmaxf(m, __shfl_xor_sync(0xffffffffu, m, o));

    __shared__ float red[8];
    if ((t & 31) == 0) red[t >> 5] = m;
    __syncthreads();
    float mm = red[0];
#pragma unroll
    for (int w = 1; w < 8; w++) mm = fmaxf(mm, red[w]);
    __syncthreads();

    float s = 0.0f;
#pragma unroll
    for (int i = 0; i < 16; i++) { v[i] = __expf(v[i] - mm); s += v[i]; }
#pragma unroll
    for (int o = 16; o > 0; o >>= 1) s += __shfl_xor_sync(0xffffffffu, s, o);
    if ((t & 31) == 0) red[t >> 5] = s;
    __syncthreads();
    float ss = 0.0f;
#pragma unroll
    for (int w = 0; w < 8; w++) ss += red[w];

    const float inv = 1.0f / ss;
#pragma unroll
    for (int i = 0; i < 16; i++) v[i] *= inv;
#pragma unroll
    for (int p = 0; p < 4; p++)
        *(float4*)&dst[(size_t)p * 1024 + t * 4] = *(float4*)&v[p * 4];
}

extern "C" void kernel_launch(void* const* d_in, const int* in_sizes, int n_in,
                              void* d_out, int out_size) {
    const float* X = (const float*)d_in[0];
    float* out     = (float*)d_out;
    (void)in_sizes; (void)n_in; (void)out_size;

    cudaFuncSetAttribute(gemm_mma, cudaFuncAttributeMaxDynamicSharedMemorySize,
                         SMEM_BYTES);

    split_bf16<<<1024, 256>>>(X);
    gemm_mma<<<dim3(NTOK / BT, NTOK / BT, NB), 256, SMEM_BYTES>>>();
    softmax_rows<<<NB * NTOK, 256>>>(out);
}

// round 4
// speedup vs baseline: 1.6550x; 1.1962x over previous
#include <cuda_runtime.h>
#include <cuda_bf16.h>

// out[b] = softmax_rows(X_b X_b^T), X: [4, 4096, 64] fp32.
// R4: k0 split X -> bf16 hi/lo; k1 mma.sync bf16 GEMM (hi*hi + hi*lo + lo*hi),
//     symmetric tiles only, fused 3-pass k-loop (frags loaded once), direct
//     .cs stores for normal tile, transposed smem stage for mirror;
//     k2 row softmax with .cs scratch read / out write.
// Harness ptxas target is sm_103 (no 'a') -> portable ldmatrix + mma.sync only.

#define NTOK 4096
#define DDIM 64
#define BT   128
#define NB   4

__device__ float         g_S [(size_t)NB * NTOK * NTOK];   // 256 MB scratch
__device__ __nv_bfloat16 g_hi[(size_t)NB * NTOK * DDIM];   // 4 MB
__device__ __nv_bfloat16 g_lo[(size_t)NB * NTOK * DDIM];   // 4 MB

#define SW128(off) ((off) ^ (((off) >> 3) & 0x70))

__device__ __forceinline__ unsigned smem_u32(const void* p) {
    unsigned a;
    asm("{ .reg .u64 t; cvta.to.shared.u64 t, %1; cvt.u32.u64 %0, t; }"
        : "=r"(a) : "l"(p));
    return a;
}
__device__ __forceinline__ void ldsm4(unsigned* r, unsigned addr) {
    asm volatile("ldmatrix.sync.aligned.m8n8.x4.shared.b16 {%0,%1,%2,%3}, [%4];"
                 : "=r"(r[0]), "=r"(r[1]), "=r"(r[2]), "=r"(r[3]) : "r"(addr));
}
__device__ __forceinline__ void mma16816(float* d, const unsigned* a,
                                         unsigned b0, unsigned b1) {
    asm volatile(
        "mma.sync.aligned.m16n8k16.row.col.f32.bf16.bf16.f32 "
        "{%0,%1,%2,%3}, {%4,%5,%6,%7}, {%8,%9}, {%0,%1,%2,%3};"
        : "+f"(d[0]), "+f"(d[1]), "+f"(d[2]), "+f"(d[3])
        : "r"(a[0]), "r"(a[1]), "r"(a[2]), "r"(a[3]), "r"(b0), "r"(b1));
}

// ---------------- k0: split fp32 -> bf16 hi + lo ----------------
__global__ __launch_bounds__(256) void split_bf16(const float* __restrict__ X) {
    size_t i = ((size_t)blockIdx.x * blockDim.x + threadIdx.x) * 4;
    float4 v = *reinterpret_cast<const float4*>(X + i);
    __nv_bfloat162 h01 = __floats2bfloat162_rn(v.x, v.y);
    __nv_bfloat162 h23 = __floats2bfloat162_rn(v.z, v.w);
    __nv_bfloat162 l01 = __floats2bfloat162_rn(v.x - __low2float(h01),
                                               v.y - __high2float(h01));
    __nv_bfloat162 l23 = __floats2bfloat162_rn(v.z - __low2float(h23),
                                               v.w - __high2float(h23));
    *reinterpret_cast<__nv_bfloat162*>(g_hi + i)     = h01;
    *reinterpret_cast<__nv_bfloat162*>(g_hi + i + 2) = h23;
    *reinterpret_cast<__nv_bfloat162*>(g_lo + i)     = l01;
    *reinterpret_cast<__nv_bfloat162*>(g_lo + i + 2) = l23;
}

// ---------------- k1: mma.sync GEMM, 128x128 tile per CTA ----------------
// dyn smem union:
//   operands: Ah @0, Al @16K, Bh @32K, Bl @48K (each 128 rows x 128 B, SW128)
//   stage:    float[128][132] (67584 B) -- used only for mirror transpose
#define STG_LD     132
#define SMEM_BYTES 67584

__device__ __forceinline__ void load_tile(char* dst, const __nv_bfloat16* src,
                                          int tid) {
    const uint4* s = reinterpret_cast<const uint4*>(src);
#pragma unroll
    for (int it = 0; it < 4; it++) {
        int i = it * 256 + tid;                 // 0..1023 16B chunks
        unsigned off = (unsigned)i * 16u;
        *reinterpret_cast<uint4*>(dst + SW128(off)) = s[i];
    }
}

__global__ __launch_bounds__(256, 2) void gemm_mma() {
    const int tj = blockIdx.x, ti = blockIdx.y, b = blockIdx.z;
    if (ti > tj) return;  // symmetric

    extern __shared__ __align__(1024) char smem[];
    float* stage = reinterpret_cast<float*>(smem);
    const unsigned sm = smem_u32(smem);

    const int tid  = threadIdx.x;
    const int wid  = tid >> 5;
    const int lane = tid & 31;
    const int mrow0 = (wid >> 1) * 32;   // 4 warp-rows of 32
    const int ncol0 = (wid & 1) * 64;    // 2 warp-cols of 64
    const bool diag = (ti == tj);

    const size_t aoff = ((size_t)b * NTOK + (size_t)ti * BT) * DDIM;
    const size_t boff = ((size_t)b * NTOK + (size_t)tj * BT) * DDIM;
    load_tile(smem,         g_hi + aoff, tid);
    load_tile(smem + 16384, g_lo + aoff, tid);
    if (!diag) {
        load_tile(smem + 32768, g_hi + boff, tid);
        load_tile(smem + 49152, g_lo + boff, tid);
    }
    __syncthreads();

    float acc[2][8][4];
#pragma unroll
    for (int mf = 0; mf < 2; mf++)
#pragma unroll
        for (int nf = 0; nf < 8; nf++)
#pragma unroll
            for (int e = 0; e < 4; e++) acc[mf][nf][e] = 0.0f;

    const int lrow  = lane & 15;          // row within 16-block
    const int lkoff = (lane >> 4) * 8;    // k half select

    const unsigned abH = sm;
    const unsigned abL = sm + 16384;
    const unsigned bbH = diag ? sm         : sm + 32768;
    const unsigned bbL = diag ? sm + 16384 : sm + 49152;

#pragma unroll
    for (int ks = 0; ks < 4; ks++) {
        const int kk = ks * 16;
        const unsigned kbyte = (unsigned)(kk + lkoff) * 2u;
        unsigned ah[2][4], al[2][4];
#pragma unroll
        for (int mf = 0; mf < 2; mf++) {
            unsigned byte = (unsigned)(mrow0 + mf * 16 + lrow) * 128u + kbyte;
            ldsm4(ah[mf], abH + SW128(byte));
            ldsm4(al[mf], abL + SW128(byte));
        }
#pragma unroll
        for (int nq = 0; nq < 4; nq++) {
            unsigned bh[4], bl[4];
            unsigned byte = (unsigned)(ncol0 + nq * 16 + lrow) * 128u + kbyte;
            ldsm4(bh, bbH + SW128(byte));
            ldsm4(bl, bbL + SW128(byte));
#pragma unroll
            for (int mf = 0; mf < 2; mf++) {
                float* d0 = acc[mf][nq * 2 + 0];
                float* d1 = acc[mf][nq * 2 + 1];
                mma16816(d0, ah[mf], bh[0], bh[2]);
                mma16816(d1, ah[mf], bh[1], bh[3]);
                mma16816(d0, ah[mf], bl[0], bl[2]);
                mma16816(d1, ah[mf], bl[1], bl[3]);
                mma16816(d0, al[mf], bh[0], bh[2]);
                mma16816(d1, al[mf], bh[1], bh[3]);
            }
        }
    }

    float* Sb = g_S + (size_t)b * NTOK * NTOK;
    const int fr = lane >> 2;          // 0..7
    const int fc = (lane & 3) * 2;     // 0,2,4,6

    // ---- normal tile: direct coalesced-per-quad float2 streaming stores ----
    {
        float* dst = Sb + (size_t)ti * BT * NTOK + (size_t)tj * BT;
#pragma unroll
        for (int mf = 0; mf < 2; mf++)
#pragma unroll
            for (int nf = 0; nf < 8; nf++) {
                int r = mrow0 + mf * 16 + fr;
                int c = ncol0 + nf * 8 + fc;
                __stcs(reinterpret_cast<float2*>(dst + (size_t)r * NTOK + c),
                       make_float2(acc[mf][nf][0], acc[mf][nf][1]));
                __stcs(reinterpret_cast<float2*>(dst + (size_t)(r + 8) * NTOK + c),
                       make_float2(acc[mf][nf][2], acc[mf][nf][3]));
            }
    }

    if (diag) return;

    // ---- mirror tile: transposed smem stage, then coalesced stores ----
    __syncthreads();  // operands dead; smem becomes stage
#pragma unroll
    for (int mf = 0; mf < 2; mf++)
#pragma unroll
        for (int nf = 0; nf < 8; nf++) {
            int r = mrow0 + mf * 16 + fr;
            int c = ncol0 + nf * 8 + fc;
            float* s0 = stage + (size_t)c * STG_LD + r;     // [c][r]
            s0[0]           = acc[mf][nf][0];
            s0[STG_LD]      = acc[mf][nf][1];               // [c+1][r]
            s0[8]           = acc[mf][nf][2];               // [c][r+8]
            s0[STG_LD + 8]  = acc[mf][nf][3];               // [c+1][r+8]
        }
    __syncthreads();
    {
        float* dst = Sb + (size_t)tj * BT * NTOK + (size_t)ti * BT;
        const int c4 = (tid & 31) * 4, rq = tid >> 5;
#pragma unroll
        for (int it = 0; it < 16; it++) {
            int r = rq + it * 8;
            float4 v = *reinterpret_cast<const float4*>(
                stage + (size_t)r * STG_LD + c4);
            __stcs(reinterpret_cast<float4*>(dst + (size_t)r * NTOK + c4), v);
        }
    }
}

// ---------------- k2: row softmax (DRAM-bound) ----------------
__global__ __launch_bounds__(256) void softmax_rows(float* __restrict__ out) {
    const size_t row = blockIdx.x;
    const float* src = g_S + row * NTOK;
    float* dst       = out + row * NTOK;
    const int t = threadIdx.x;

    float v[16];
#pragma unroll
    for (int p = 0; p < 4; p++) {
        float4 x = __ldcs(reinterpret_cast<const float4*>(
            src + (size_t)p * 1024 + t * 4));
        v[p * 4 + 0] = x.x; v[p * 4 + 1] = x.y;
        v[p * 4 + 2] = x.z; v[p * 4 + 3] = x.w;
    }

    float m = v[0];
#pragma unroll
    for (int i = 1; i < 16; i++) m = fmaxf(m, v[i]);
#pragma unroll
    for (int o = 16; o > 0; o >>= 1) m = fmaxf(m, __shfl_xor_sync(0xffffffffu, m, o));

    __shared__ float red[8];
    if ((t & 31) == 0) red[t >> 5] = m;
    __syncthreads();
    float mm = red[0];
#pragma unroll
    for (int w = 1; w < 8; w++) mm = fmaxf(mm, red[w]);
    __syncthreads();

    float s = 0.0f;
#pragma unroll
    for (int i = 0; i < 16; i++) { v[i] = __expf(v[i] - mm); s += v[i]; }
#pragma unroll
    for (int o = 16; o > 0; o >>= 1) s += __shfl_xor_sync(0xffffffffu, s, o);
    if ((t & 31) == 0) red[t >> 5] = s;
    __syncthreads();
    float ss = 0.0f;
#pragma unroll
    for (int w = 0; w < 8; w++) ss += red[w];

    const float inv = 1.0f / ss;
#pragma unroll
    for (int i = 0; i < 16; i++) v[i] *= inv;
#pragma unroll
    for (int p = 0; p < 4; p++)
        __stcs(reinterpret_cast<float4*>(dst + (size_t)p * 1024 + t * 4),
               make_float4(v[p * 4 + 0], v[p * 4 + 1], v[p * 4 + 2], v[p * 4 + 3]));
}

extern "C" void kernel_launch(void* const* d_in, const int* in_sizes, int n_in,
                              void* d_out, int out_size) {
    const float* X = (const float*)d_in[0];
    float* out     = (float*)d_out;
    (void)in_sizes; (void)n_in; (void)out_size;

    cudaFuncSetAttribute(gemm_mma, cudaFuncAttributeMaxDynamicSharedMemorySize,
                         SMEM_BYTES);

    split_bf16<<<1024, 256>>>(X);
    gemm_mma<<<dim3(NTOK / BT, NTOK / BT, NB), 256, SMEM_BYTES>>>();
    softmax_rows<<<NB * NTOK, 256>>>(out);
}